// round 1
// baseline (speedup 1.0000x reference)
#include <cuda_runtime.h>

#define B_VOX   256
#define NPC     40
#define NE      32
#define WARPS   20          // 2 compartments per warp
#define THREADS (WARPS * 32)

// EPG recurrence: x' = D * S * T * D * S * x, with state per order o:
//   lane t (t = 0..31) holds block o = t+1: F = x[1+3t], G = x[2+3t], Z = x[3+3t]
//   lane 0 additionally holds x0 = x[0].
// Shift S:  newF[t] = (t==0 ? x0 : F[t-1]);  newG[t] = (t==31 ? 0 : G[t+1]);
//           newZ[t] = Z[t];  new_x0 = G[0].
// Decay D:  F,G,x0 *= e2;  Z *= e1  (e1 = exp(-tau/T1) const).
// Rotation T (per voxel): [c2 s2 s; s2 c2 -s; -s/2 s/2 c].
// Echo_k = x0 after k+1 applications. Output normalized by echo_0.

__global__ __launch_bounds__(THREADS) void epg_kernel(
    const float* __restrict__ refoc,    // (256,)
    const float* __restrict__ t2s,      // (256, 40)
    const float* __restrict__ wts,      // (256, 40)
    float* __restrict__ out)            // (256, 32)
{
    const int b    = blockIdx.x;
    const int lane = threadIdx.x & 31;
    const int wz   = threadIdx.x >> 5;
    const unsigned FULL = 0xFFFFFFFFu;

    __shared__ float smem[WARPS * 32];

    // Per-voxel rotation constants
    const float a  = refoc[b] * 0.017453292519943295f;   // deg -> rad
    const float ah = 0.5f * a;                           // excitation flip
    const float sa = sinf(a),  ca = cosf(a);
    const float sh = sinf(ah), ch = cosf(ah);
    const float c2 = ch * ch, s2 = sh * sh;
    const float e1 = 0.99501247919268231f;               // exp(-5/1000)

    // Two compartments per warp
    const int c0 = 2 * wz, c1 = 2 * wz + 1;
    const float w0  = wts[b * NPC + c0];
    const float w1  = wts[b * NPC + c1];
    const float e2a = expf(-5.0f / t2s[b * NPC + c0]);
    const float e2b = expf(-5.0f / t2s[b * NPC + c1]);

    // Initial state: x[0] = sin(ah), x[2] = G[0] = cos(ah)
    float x0a = sh, Fa = 0.f, Ga = (lane == 0) ? ch : 0.f, Za = 0.f;
    float x0b = sh, Fb = 0.f, Gb = (lane == 0) ? ch : 0.f, Zb = 0.f;
    float acc = 0.f;

    #pragma unroll
    for (int k = 0; k < NE; ++k) {
        // ---- shift 1 + decay ----
        float Fua = __shfl_up_sync(FULL, Fa, 1);
        float Gda = __shfl_down_sync(FULL, Ga, 1);
        float Fub = __shfl_up_sync(FULL, Fb, 1);
        float Gdb = __shfl_down_sync(FULL, Gb, 1);

        float mx0a = Ga * e2a;                                  // x0_B (lane 0)
        float mFa  = ((lane == 0) ? x0a : Fua) * e2a;
        float mGa  = ((lane == 31) ? 0.f : Gda) * e2a;
        float mZa  = Za * e1;
        float mx0b = Gb * e2b;
        float mFb  = ((lane == 0) ? x0b : Fub) * e2b;
        float mGb  = ((lane == 31) ? 0.f : Gdb) * e2b;
        float mZb  = Zb * e1;

        // ---- rotation T ----
        float rFa = fmaf(c2, mFa, fmaf(s2, mGa,  sa * mZa));
        float rGa = fmaf(s2, mFa, fmaf(c2, mGa, -sa * mZa));
        float rZa = fmaf(-0.5f * sa, mFa, fmaf(0.5f * sa, mGa, ca * mZa));
        float rFb = fmaf(c2, mFb, fmaf(s2, mGb,  sa * mZb));
        float rGb = fmaf(s2, mFb, fmaf(c2, mGb, -sa * mZb));
        float rZb = fmaf(-0.5f * sa, mFb, fmaf(0.5f * sa, mGb, ca * mZb));

        // ---- shift 2 + decay ----
        Fua = __shfl_up_sync(FULL, rFa, 1);
        Gda = __shfl_down_sync(FULL, rGa, 1);
        Fub = __shfl_up_sync(FULL, rFb, 1);
        Gdb = __shfl_down_sync(FULL, rGb, 1);

        x0a = rGa * e2a;                                        // echo (lane 0)
        Fa  = ((lane == 0) ? mx0a : Fua) * e2a;
        Ga  = ((lane == 31) ? 0.f : Gda) * e2a;
        Za  = rZa * e1;
        x0b = rGb * e2b;
        Fb  = ((lane == 0) ? mx0b : Fub) * e2b;
        Gb  = ((lane == 31) ? 0.f : Gdb) * e2b;
        Zb  = rZb * e1;

        // ---- weighted echo: park echo k in lane k ----
        float wh = fmaf(w0, x0a, w1 * x0b);
        float h  = __shfl_sync(FULL, wh, 0);
        if (lane == k) acc = h;
    }

    // Reduce over the 20 warps (compartment sum), normalize by echo 0
    smem[wz * 32 + lane] = acc;
    __syncthreads();
    if (threadIdx.x < 32) {
        float s = 0.f;
        #pragma unroll
        for (int w = 0; w < WARPS; ++w) s += smem[w * 32 + lane];
        float s0 = __shfl_sync(FULL, s, 0);
        out[b * NE + lane] = s / s0;
    }
}

extern "C" void kernel_launch(void* const* d_in, const int* in_sizes, int n_in,
                              void* d_out, int out_size) {
    const float* refoc = (const float*)d_in[0];
    const float* t2s   = (const float*)d_in[1];
    const float* wts   = (const float*)d_in[2];
    float* out = (float*)d_out;
    epg_kernel<<<B_VOX, THREADS>>>(refoc, t2s, wts, out);
}

// round 2
// speedup vs baseline: 1.6911x; 1.6911x over previous
#include <cuda_runtime.h>

#define B_VOX   256
#define NPC     40
#define NE      32
#define CPW     4                    // compartments per warp (ILP)
#define WARPS   (NPC / CPW)          // 10
#define THREADS (WARPS * 32)

// EPG step: x' = E x, E = D·S·T·D·S = S·(D·T·D)·S  (D commutes with S since
// the shift maps only between slots sharing the same decay value).
// lane t holds EPG order t+1 as (F,G,Z); x0 lives logically in lane 0.
// M = D·T·D per compartment:
//   F' =  A·F + B·G + C·Z
//   G' =  B·F + A·G - C·Z
//   Z' =  Dz·(G-F) + Ez·Z
//   x0' = e2^2 · x0
// with A=c2·e2^2, B=s2·e2^2, C=s·e2·e1, Dz=0.5·s·e1·e2, Ez=c·e1^2.
// Echo k = lane0's G' (i.e. mG before the second shift).

__global__ __launch_bounds__(THREADS) void epg_kernel(
    const float* __restrict__ refoc,    // (256,)
    const float* __restrict__ t2s,      // (256, 40)
    const float* __restrict__ wts,      // (256, 40)
    float* __restrict__ out)            // (256, 32)
{
    const int b    = blockIdx.x;
    const int lane = threadIdx.x & 31;
    const int wz   = threadIdx.x >> 5;
    const bool l0  = (lane == 0);
    const bool l31 = (lane == 31);
    const unsigned FULL = 0xFFFFFFFFu;

    __shared__ float smem[WARPS * NE];

    // per-voxel rotation constants
    const float a  = refoc[b] * 0.017453292519943295f;
    const float ah = 0.5f * a;
    const float sa = sinf(a),  ca = cosf(a);
    const float sh = sinf(ah), ch = cosf(ah);
    const float c2 = ch * ch,  s2 = sh * sh;
    const float e1   = 0.99501247919268231f;     // exp(-5/1000)
    const float e1sq = e1 * e1;

    // per-compartment fused coefficients
    float A[CPW], Bc[CPW], Cc[CPW], Dz[CPW], Ez[CPW], e2q[CPW], w[CPW];
    #pragma unroll
    for (int i = 0; i < CPW; ++i) {
        const int c = wz * CPW + i;
        const float e2   = expf(-5.0f / t2s[b * NPC + c]);
        const float e2sq = e2 * e2;
        A[i]   = c2 * e2sq;
        Bc[i]  = s2 * e2sq;
        Cc[i]  = sa * e2 * e1;
        Dz[i]  = 0.5f * sa * e1 * e2;
        Ez[i]  = ca * e1sq;
        e2q[i] = e2sq;
        w[i]   = wts[b * NPC + c];
    }

    // initial state: x0 = sin(ah); G(order1, lane0) = cos(ah)
    float F[CPW], G[CPW], Z[CPW], x0[CPW];
    #pragma unroll
    for (int i = 0; i < CPW; ++i) {
        F[i]  = 0.0f;
        G[i]  = l0 ? ch : 0.0f;
        Z[i]  = 0.0f;
        x0[i] = sh;
    }

    #pragma unroll 4
    for (int k = 0; k < NE; ++k) {
        float wh = 0.0f;
        #pragma unroll
        for (int i = 0; i < CPW; ++i) {
            // shift 1
            const float Fu = __shfl_up_sync(FULL, F[i], 1);
            const float Gd = __shfl_down_sync(FULL, G[i], 1);
            const float sF = l0  ? x0[i] : Fu;
            const float sG = l31 ? 0.0f  : Gd;
            const float mx0 = e2q[i] * G[i];          // lane0: uses its own pre-shift G
            // M = D·T·D
            const float t  = Cc[i] * Z[i];
            const float mF = fmaf(A[i],  sF, fmaf(Bc[i], sG,  t));
            const float mG = fmaf(Bc[i], sF, fmaf(A[i],  sG, -t));
            const float mZ = fmaf(Ez[i], Z[i], Dz[i] * (sG - sF));
            // shift 2
            const float mFu = __shfl_up_sync(FULL, mF, 1);
            const float mGd = __shfl_down_sync(FULL, mG, 1);
            F[i]  = l0  ? mx0 : mFu;
            G[i]  = l31 ? 0.0f : mGd;
            Z[i]  = mZ;
            x0[i] = mG;                               // new x0 (lane0's mG)
            wh = fmaf(w[i], mG, wh);                  // weighted echo contribution
        }
        if (l0) smem[wz * NE + k] = wh;               // hoisted predicate, 1 STS
    }

    __syncthreads();

    // warp 0: sum over the 10 warps, normalize by echo 0
    if (threadIdx.x < 32) {
        float s = 0.0f;
        #pragma unroll
        for (int ww = 0; ww < WARPS; ++ww) s += smem[ww * NE + lane];
        const float s0 = __shfl_sync(FULL, s, 0);
        out[b * NE + lane] = s / s0;
    }
}

extern "C" void kernel_launch(void* const* d_in, const int* in_sizes, int n_in,
                              void* d_out, int out_size) {
    const float* refoc = (const float*)d_in[0];
    const float* t2s   = (const float*)d_in[1];
    const float* wts   = (const float*)d_in[2];
    float* out = (float*)d_out;
    epg_kernel<<<B_VOX, THREADS>>>(refoc, t2s, wts, out);
}

// round 3
// speedup vs baseline: 2.7964x; 1.6536x over previous
#include <cuda_runtime.h>

#define B_VOX   256
#define NPC     40
#define NE      32
#define ORD     4                    // EPG orders per lane
#define LPC     8                    // lanes per compartment (ORD*LPC = 32 orders)
#define CPW     4                    // compartments per warp
#define WARPS   (NPC / CPW)          // 10
#define THREADS (WARPS * 32)

// EPG step x' = S·(D·T·D)·S·x (D commutes with S). Order o = 4*s + j + 1,
// sub-lane s = lane&7 (0..7), j = 0..3; compartment = wz*4 + (lane>>3).
// Per-compartment fused 3x3:  mF =  A·sF + B·sG + C·Z
//                             mG =  B·sF + A·sG - C·Z
//                             mZ =  Dz·(sG - sF) + Ez·Z
// shift1: sF[o]=F[o-1] (sF[1]=x0),  sG[o]=G[o+1] (sG[32]=0),  mx0=e2²·G[1]
// shift2: F[o]=mF[o-1] (F[1]=mx0),  G[o]=mG[o+1] (G[32]=0),   x0=mG[1]=echo

__global__ __launch_bounds__(THREADS) void epg_kernel(
    const float* __restrict__ refoc,    // (256,)
    const float* __restrict__ t2s,      // (256, 40)
    const float* __restrict__ wts,      // (256, 40)
    float* __restrict__ out)            // (256, 32)
{
    const int b    = blockIdx.x;
    const int lane = threadIdx.x & 31;
    const int wz   = threadIdx.x >> 5;
    const int s    = lane & (LPC - 1);       // sub-lane within compartment
    const int grp  = lane >> 3;              // compartment group within warp
    const bool sLo = (s == 0);
    const bool sHi = (s == LPC - 1);
    const unsigned FULL = 0xFFFFFFFFu;

    __shared__ float smem[NPC][NE + 1];      // +1 pad: conflict-free leader STS

    // per-voxel rotation constants
    const float a  = refoc[b] * 0.017453292519943295f;
    const float ah = 0.5f * a;
    const float sa = sinf(a),  ca = cosf(a);
    const float sh = sinf(ah), ch = cosf(ah);
    const float c2 = ch * ch,  s2 = sh * sh;
    const float e1   = 0.99501247919268231f;     // exp(-5/1000)
    const float e1sq = e1 * e1;

    // per-compartment fused coefficients
    const int   c    = wz * CPW + grp;
    const float e2   = expf(-5.0f / t2s[b * NPC + c]);
    const float e2sq = e2 * e2;
    const float A    = c2 * e2sq;
    const float Bc   = s2 * e2sq;
    const float Cc   = sa * e2 * e1;
    const float Dz   = 0.5f * sa * e1 * e2;
    const float Ez   = ca * e1sq;
    const float w    = wts[b * NPC + c];

    // initial state: x0 = sin(ah); G(order 1) = cos(ah)
    float F[ORD] = {0.f, 0.f, 0.f, 0.f};
    float G[ORD] = {sLo ? ch : 0.f, 0.f, 0.f, 0.f};
    float Z[ORD] = {0.f, 0.f, 0.f, 0.f};
    float x0 = sh;                                // meaningful on sub-lane 0

    #pragma unroll 4
    for (int k = 0; k < NE; ++k) {
        // ---- shift 1: only the boundary element crosses lanes ----
        const float fc = __shfl_up_sync  (FULL, F[ORD-1], 1, LPC);
        const float gc = __shfl_down_sync(FULL, G[0],     1, LPC);
        const float mx0 = e2sq * G[0];            // sub-lane 0: order-1 G pre-shift

        float sF[ORD], sG[ORD];
        sF[0] = sLo ? x0 : fc;
        sF[1] = F[0]; sF[2] = F[1]; sF[3] = F[2];
        sG[0] = G[1]; sG[1] = G[2]; sG[2] = G[3];
        sG[3] = sHi ? 0.f : gc;

        // ---- fused rotation+decay ----
        float mF[ORD], mG[ORD], mZ[ORD];
        #pragma unroll
        for (int j = 0; j < ORD; ++j) {
            const float t = Cc * Z[j];
            mF[j] = fmaf(A,  sF[j], fmaf(Bc, sG[j],  t));
            mG[j] = fmaf(Bc, sF[j], fmaf(A,  sG[j], -t));
            mZ[j] = fmaf(Ez, Z[j], Dz * (sG[j] - sF[j]));
        }

        // ---- shift 2 ----
        const float fc2 = __shfl_up_sync  (FULL, mF[ORD-1], 1, LPC);
        const float gc2 = __shfl_down_sync(FULL, mG[0],     1, LPC);
        F[0] = sLo ? mx0 : fc2;
        F[1] = mF[0]; F[2] = mF[1]; F[3] = mF[2];
        G[0] = mG[1]; G[1] = mG[2]; G[2] = mG[3];
        G[3] = sHi ? 0.f : gc2;
        Z[0] = mZ[0]; Z[1] = mZ[1]; Z[2] = mZ[2]; Z[3] = mZ[3];
        x0 = mG[0];                               // new x0 (= echo on sub-lane 0)

        if (sLo) smem[c][k] = w * mG[0];          // weighted echo, 1 predicated STS
    }

    __syncthreads();

    // warp 0: sum 40 compartments per echo, normalize by echo 0
    if (threadIdx.x < 32) {
        float acc = 0.0f;
        #pragma unroll
        for (int r = 0; r < NPC; ++r) acc += smem[r][lane];
        const float acc0 = __shfl_sync(FULL, acc, 0);
        out[b * NE + lane] = acc / acc0;
    }
}

extern "C" void kernel_launch(void* const* d_in, const int* in_sizes, int n_in,
                              void* d_out, int out_size) {
    const float* refoc = (const float*)d_in[0];
    const float* t2s   = (const float*)d_in[1];
    const float* wts   = (const float*)d_in[2];
    float* out = (float*)d_out;
    epg_kernel<<<B_VOX, THREADS>>>(refoc, t2s, wts, out);
}